// round 13
// baseline (speedup 1.0000x reference)
#include <cuda_runtime.h>

// Fixed shapes: pred[8192,7,7,30], gt[8192,7,7,30]
// 401408 cells = 12544 warp-tiles of 32 cells
#define NCH        30
#define TPB        128
#define NWARPS_CTA 4
#define GRID_BLOCKS 456                       // 152 SMs * 3 CTAs -> one wave
#define WT_F4      240                        // 32 cells * 30 ch / 4 (per tensor)
#define STAGE_F4   (2 * WT_F4)                // 480 f4 = 7680 B (pred + gt)
#define WARP_SMEM_F4 (2 * STAGE_F4)           // double buffer = 960 f4
#define SMEM_BYTES (NWARPS_CTA * WARP_SMEM_F4 * 16)   // 61440 B
#define MAX_PART   1024

__device__ float        g_partials[MAX_PART];
__device__ unsigned int g_count = 0;

__device__ __forceinline__ float cell_loss(const float* __restrict__ p,
                                           const float* __restrict__ g)
{
    const float gx = g[0], gy = g[1], gw = g[2], gh = g[3];
    const float obj   = (g[4] > 0.0f) ? 1.0f : 0.0f;
    const float noobj = 1.0f - obj;

    const float pc0 = p[4];
    const float pc1 = p[9];

    const float no_obj_term = noobj * (pc0 * pc0 + pc1 * pc1);

    const float ghw = 3.5f * gw, ghh = 3.5f * gh;
    const float gx1 = gx - ghw, gx2 = gx + ghw;
    const float gy1 = gy - ghh, gy2 = gy + ghh;
    const float a2  = 49.0f * gw * gh;

    float iou[2];
    #pragma unroll
    for (int b = 0; b < 2; b++) {
        const float cx = p[b*5+0], cy = p[b*5+1];
        const float w  = p[b*5+2], h  = p[b*5+3];
        const float hw = 3.5f * w, hh = 3.5f * h;
        const float iw = fmaxf(fminf(cx + hw, gx2) - fmaxf(cx - hw, gx1), 0.0f);
        const float ih = fmaxf(fminf(cy + hh, gy2) - fmaxf(cy - hh, gy1), 0.0f);
        const float inter = iw * ih;
        const float a1 = 49.0f * w * h;
        iou[b] = inter / (a1 + a2 - inter);
    }

    const int   r       = (iou[1] > iou[0]) ? 1 : 0;
    const float max_iou = fmaxf(iou[0], iou[1]);
    const float* pr     = p + r * 5;
    const float pc_irr  = r ? pc0 : pc1;

    const float dx = pr[0] - gx;
    const float dy = pr[1] - gy;
    const float dw = sqrtf(pr[2]) - sqrtf(gw);
    const float dh = sqrtf(pr[3]) - sqrtf(gh);
    const float coord = dx*dx + dy*dy + dw*dw + dh*dh;

    const float dr = pr[4] - max_iou;
    const float resp_l   = dr * dr;
    const float irresp_l = pc_irr * pc_irr;

    float cls = 0.0f;
    #pragma unroll
    for (int c = 10; c < 30; c++) {
        const float d = p[c] - g[c];
        cls = fmaf(d, d, cls);
    }

    return obj * (5.0f * coord + 2.0f * resp_l + irresp_l + cls)
         + 0.5f * no_obj_term;
}

__global__ __launch_bounds__(TPB)
void yolo_loss_warp_pipe(const float4* __restrict__ pred4,
                         const float4* __restrict__ gt4,
                         float* __restrict__ out,
                         int n_wtiles, int n_wpipes, float inv_batch)
{
    extern __shared__ float4 smem[];           // [4 warps][2 bufs][480 f4]
    const int tid  = threadIdx.x;
    const int lane = tid & 31;
    const int wid  = tid >> 5;
    float4* wsm = smem + wid * WARP_SMEM_F4;

    // Asymmetric L2 policy: gt (48 MB) pinned evict_last -> retained across
    // graph replays; pred (48 MB) evict_first -> streams without displacing gt.
    unsigned long long polLast, polFirst;
    asm volatile("createpolicy.fractional.L2::evict_last.b64 %0, 1.0;"
                 : "=l"(polLast));
    asm volatile("createpolicy.fractional.L2::evict_first.b64 %0, 1.0;"
                 : "=l"(polFirst));

    // ---- per-warp async stage: one 32-cell tile into buffer `buf` ----
    auto issue = [&](int tile, int buf) {
        const float4* psrc = pred4 + (long long)tile * WT_F4;
        const float4* gsrc = gt4   + (long long)tile * WT_F4;
        float4* dst = wsm + buf * STAGE_F4;
        #pragma unroll
        for (int k = 0; k < STAGE_F4 / 32; k++) {          // 15 per lane
            const int i = lane + k * 32;
            unsigned saddr = (unsigned)__cvta_generic_to_shared(dst + i);
            if (i < WT_F4) {
                asm volatile(
                    "cp.async.cg.shared.global.L2::cache_hint [%0], [%1], 16, %2;"
                    :: "r"(saddr), "l"(psrc + i), "l"(polFirst));
            } else {
                asm volatile(
                    "cp.async.cg.shared.global.L2::cache_hint [%0], [%1], 16, %2;"
                    :: "r"(saddr), "l"(gsrc + (i - WT_F4)), "l"(polLast));
            }
        }
        asm volatile("cp.async.commit_group;" ::: "memory");
    };

    float acc = 0.0f;
    const int gw = blockIdx.x * NWARPS_CTA + wid;   // global warp-pipeline id
    int t   = gw;
    int buf = 0;

    if (t < n_wtiles) issue(t, 0);

    while (t < n_wtiles) {
        const int tn = t + n_wpipes;
        if (tn < n_wtiles) {
            issue(tn, buf ^ 1);
            asm volatile("cp.async.wait_group 1;" ::: "memory");
        } else {
            asm volatile("cp.async.wait_group 0;" ::: "memory");
        }
        __syncwarp();   // cp.async writes visible across the warp

        const float* base = reinterpret_cast<const float*>(wsm + buf * STAGE_F4);
        acc += cell_loss(base + lane * NCH,
                         base + WT_F4 * 4 + lane * NCH);

        __syncwarp();   // compute reads done before buf is refilled
        buf ^= 1;
        t = tn;
    }

    // ---- per-warp then block reduction (deterministic) ----
    #pragma unroll
    for (int o = 16; o > 0; o >>= 1)
        acc += __shfl_down_sync(0xffffffffu, acc, o);

    __shared__ float s_warp[NWARPS_CTA];
    if (lane == 0) s_warp[wid] = acc;
    __syncthreads();

    __shared__ bool s_is_last;
    if (tid == 0) {
        g_partials[blockIdx.x] = s_warp[0] + s_warp[1] + s_warp[2] + s_warp[3];
        __threadfence();
        unsigned int done = atomicAdd(&g_count, 1u);
        s_is_last = (done == (unsigned int)(gridDim.x - 1));
    }
    __syncthreads();

    // ---- last block folds the partials (fixed order -> deterministic) ----
    if (s_is_last) {
        float v = 0.0f;
        for (int i = tid; i < (int)gridDim.x; i += TPB)
            v += g_partials[i];

        #pragma unroll
        for (int o = 16; o > 0; o >>= 1)
            v += __shfl_down_sync(0xffffffffu, v, o);

        if (lane == 0) s_warp[wid] = v;
        __syncthreads();
        if (tid == 0) {
            out[0] = (s_warp[0] + s_warp[1] + s_warp[2] + s_warp[3]) * inv_batch;
            g_count = 0;   // reset for next graph replay
        }
    }
}

extern "C" void kernel_launch(void* const* d_in, const int* in_sizes, int n_in,
                              void* d_out, int out_size)
{
    const float4* pred4 = (const float4*)d_in[0];
    const float4* gt4   = (const float4*)d_in[1];
    float* out = (float*)d_out;

    const int n_cells  = in_sizes[0] / NCH;       // 401408
    const int n_wtiles = n_cells / 32;            // 12544 (exact)
    const int n_wpipes = GRID_BLOCKS * NWARPS_CTA;// 1824
    const int batch    = n_cells / 49;            // 8192

    cudaFuncSetAttribute(yolo_loss_warp_pipe,
                         cudaFuncAttributeMaxDynamicSharedMemorySize, SMEM_BYTES);

    yolo_loss_warp_pipe<<<GRID_BLOCKS, TPB, SMEM_BYTES>>>(pred4, gt4, out,
                                                          n_wtiles, n_wpipes,
                                                          1.0f / (float)batch);
}

// round 14
// speedup vs baseline: 1.0577x; 1.0577x over previous
#include <cuda_runtime.h>

// Fixed shapes: pred[8192,7,7,30], gt[8192,7,7,30]
// 401408 cells = 12544 warp-tiles of 32 cells
#define NCH        30
#define TPB        128
#define NWARPS_CTA 4
#define GRID_BLOCKS 456                       // 152 SMs * 3 CTAs -> one wave
#define WT_F4      240                        // 32 cells * 30 ch / 4 (per tensor)
#define STAGE_F4   (2 * WT_F4)                // 480 f4 = 7680 B (pred + gt)
#define WARP_SMEM_F4 (2 * STAGE_F4)           // double buffer = 960 f4
#define SMEM_BYTES (NWARPS_CTA * WARP_SMEM_F4 * 16)   // 61440 B
#define MAX_PART   1024

__device__ float        g_partials[MAX_PART];
__device__ unsigned int g_count = 0;

__device__ __forceinline__ float cell_loss(const float* __restrict__ p,
                                           const float* __restrict__ g)
{
    const float gx = g[0], gy = g[1], gw = g[2], gh = g[3];
    const float obj   = (g[4] > 0.0f) ? 1.0f : 0.0f;
    const float noobj = 1.0f - obj;

    const float pc0 = p[4];
    const float pc1 = p[9];

    const float no_obj_term = noobj * (pc0 * pc0 + pc1 * pc1);

    const float ghw = 3.5f * gw, ghh = 3.5f * gh;
    const float gx1 = gx - ghw, gx2 = gx + ghw;
    const float gy1 = gy - ghh, gy2 = gy + ghh;
    const float a2  = 49.0f * gw * gh;

    float iou[2];
    #pragma unroll
    for (int b = 0; b < 2; b++) {
        const float cx = p[b*5+0], cy = p[b*5+1];
        const float w  = p[b*5+2], h  = p[b*5+3];
        const float hw = 3.5f * w, hh = 3.5f * h;
        const float iw = fmaxf(fminf(cx + hw, gx2) - fmaxf(cx - hw, gx1), 0.0f);
        const float ih = fmaxf(fminf(cy + hh, gy2) - fmaxf(cy - hh, gy1), 0.0f);
        const float inter = iw * ih;
        const float a1 = 49.0f * w * h;
        iou[b] = inter / (a1 + a2 - inter);
    }

    const int   r       = (iou[1] > iou[0]) ? 1 : 0;
    const float max_iou = fmaxf(iou[0], iou[1]);
    const float* pr     = p + r * 5;
    const float pc_irr  = r ? pc0 : pc1;

    const float dx = pr[0] - gx;
    const float dy = pr[1] - gy;
    const float dw = sqrtf(pr[2]) - sqrtf(gw);
    const float dh = sqrtf(pr[3]) - sqrtf(gh);
    const float coord = dx*dx + dy*dy + dw*dw + dh*dh;

    const float dr = pr[4] - max_iou;
    const float resp_l   = dr * dr;
    const float irresp_l = pc_irr * pc_irr;

    float cls = 0.0f;
    #pragma unroll
    for (int c = 10; c < 30; c++) {
        const float d = p[c] - g[c];
        cls = fmaf(d, d, cls);
    }

    return obj * (5.0f * coord + 2.0f * resp_l + irresp_l + cls)
         + 0.5f * no_obj_term;
}

__global__ __launch_bounds__(TPB)
void yolo_loss_warp_pipe(const float4* __restrict__ pred4,
                         const float4* __restrict__ gt4,
                         float* __restrict__ out,
                         int n_wtiles, int n_wpipes, float inv_batch)
{
    extern __shared__ float4 smem[];           // [4 warps][2 bufs][480 f4]
    const int tid  = threadIdx.x;
    const int lane = tid & 31;
    const int wid  = tid >> 5;
    float4* wsm = smem + wid * WARP_SMEM_F4;

    // ---- per-warp async stage: one 32-cell tile into buffer `buf` ----
    auto issue = [&](int tile, int buf) {
        const float4* psrc = pred4 + (long long)tile * WT_F4;
        const float4* gsrc = gt4   + (long long)tile * WT_F4;
        float4* dst = wsm + buf * STAGE_F4;
        #pragma unroll
        for (int k = 0; k < STAGE_F4 / 32; k++) {          // 15 per lane
            const int i = lane + k * 32;
            const float4* src = (i < WT_F4) ? (psrc + i) : (gsrc + (i - WT_F4));
            unsigned saddr = (unsigned)__cvta_generic_to_shared(dst + i);
            asm volatile("cp.async.cg.shared.global [%0], [%1], 16;"
                         :: "r"(saddr), "l"(src));
        }
        asm volatile("cp.async.commit_group;" ::: "memory");
    };

    float acc = 0.0f;
    const int gw = blockIdx.x * NWARPS_CTA + wid;   // global warp-pipeline id
    int t   = gw;
    int buf = 0;

    if (t < n_wtiles) issue(t, 0);

    while (t < n_wtiles) {
        const int tn = t + n_wpipes;
        if (tn < n_wtiles) {
            issue(tn, buf ^ 1);
            asm volatile("cp.async.wait_group 1;" ::: "memory");
        } else {
            asm volatile("cp.async.wait_group 0;" ::: "memory");
        }
        __syncwarp();   // cp.async writes visible across the warp

        const float* base = reinterpret_cast<const float*>(wsm + buf * STAGE_F4);
        acc += cell_loss(base + lane * NCH,
                         base + WT_F4 * 4 + lane * NCH);

        __syncwarp();   // compute reads done before buf is refilled
        buf ^= 1;
        t = tn;
    }

    // ---- per-warp then block reduction (deterministic) ----
    #pragma unroll
    for (int o = 16; o > 0; o >>= 1)
        acc += __shfl_down_sync(0xffffffffu, acc, o);

    __shared__ float s_warp[NWARPS_CTA];
    if (lane == 0) s_warp[wid] = acc;
    __syncthreads();

    __shared__ bool s_is_last;
    if (tid == 0) {
        g_partials[blockIdx.x] = s_warp[0] + s_warp[1] + s_warp[2] + s_warp[3];
        __threadfence();
        unsigned int done = atomicAdd(&g_count, 1u);
        s_is_last = (done == (unsigned int)(gridDim.x - 1));
    }
    __syncthreads();

    // ---- last block folds the partials (fixed order -> deterministic) ----
    if (s_is_last) {
        float v = 0.0f;
        for (int i = tid; i < (int)gridDim.x; i += TPB)
            v += g_partials[i];

        #pragma unroll
        for (int o = 16; o > 0; o >>= 1)
            v += __shfl_down_sync(0xffffffffu, v, o);

        if (lane == 0) s_warp[wid] = v;
        __syncthreads();
        if (tid == 0) {
            out[0] = (s_warp[0] + s_warp[1] + s_warp[2] + s_warp[3]) * inv_batch;
            g_count = 0;   // reset for next graph replay
        }
    }
}

extern "C" void kernel_launch(void* const* d_in, const int* in_sizes, int n_in,
                              void* d_out, int out_size)
{
    const float4* pred4 = (const float4*)d_in[0];
    const float4* gt4   = (const float4*)d_in[1];
    float* out = (float*)d_out;

    const int n_cells  = in_sizes[0] / NCH;       // 401408
    const int n_wtiles = n_cells / 32;            // 12544 (exact)
    const int n_wpipes = GRID_BLOCKS * NWARPS_CTA;// 1824
    const int batch    = n_cells / 49;            // 8192

    cudaFuncSetAttribute(yolo_loss_warp_pipe,
                         cudaFuncAttributeMaxDynamicSharedMemorySize, SMEM_BYTES);

    yolo_loss_warp_pipe<<<GRID_BLOCKS, TPB, SMEM_BYTES>>>(pred4, gt4, out,
                                                          n_wtiles, n_wpipes,
                                                          1.0f / (float)batch);
}

// round 15
// speedup vs baseline: 1.0869x; 1.0275x over previous
#include <cuda_runtime.h>

// Fixed shapes: pred[8192,7,7,30], gt[8192,7,7,30]
// 401408 cells = 12544 warp-tiles of 32 cells
#define NCH        30
#define TPB        128
#define NWARPS_CTA 4
#define GRID_BLOCKS 456                       // 152 SMs * 3 CTAs -> one wave
#define WT_BYTES   3840                       // 32 cells * 30 ch * 4 B (per tensor)
#define STAGE_BYTES (2 * WT_BYTES)            // 7680 B (pred + gt)
#define WARP_SMEM_BYTES (2 * STAGE_BYTES)     // double buffer = 15360 B
#define SMEM_BYTES (NWARPS_CTA * WARP_SMEM_BYTES)   // 61440 B
#define MAX_PART   1024

__device__ float        g_partials[MAX_PART];
__device__ unsigned int g_count = 0;

__device__ __forceinline__ float cell_loss(const float* __restrict__ p,
                                           const float* __restrict__ g)
{
    const float gx = g[0], gy = g[1], gw = g[2], gh = g[3];
    const float obj   = (g[4] > 0.0f) ? 1.0f : 0.0f;
    const float noobj = 1.0f - obj;

    const float pc0 = p[4];
    const float pc1 = p[9];

    const float no_obj_term = noobj * (pc0 * pc0 + pc1 * pc1);

    const float ghw = 3.5f * gw, ghh = 3.5f * gh;
    const float gx1 = gx - ghw, gx2 = gx + ghw;
    const float gy1 = gy - ghh, gy2 = gy + ghh;
    const float a2  = 49.0f * gw * gh;

    float iou[2];
    #pragma unroll
    for (int b = 0; b < 2; b++) {
        const float cx = p[b*5+0], cy = p[b*5+1];
        const float w  = p[b*5+2], h  = p[b*5+3];
        const float hw = 3.5f * w, hh = 3.5f * h;
        const float iw = fmaxf(fminf(cx + hw, gx2) - fmaxf(cx - hw, gx1), 0.0f);
        const float ih = fmaxf(fminf(cy + hh, gy2) - fmaxf(cy - hh, gy1), 0.0f);
        const float inter = iw * ih;
        const float a1 = 49.0f * w * h;
        iou[b] = inter / (a1 + a2 - inter);
    }

    const int   r       = (iou[1] > iou[0]) ? 1 : 0;
    const float max_iou = fmaxf(iou[0], iou[1]);
    const float* pr     = p + r * 5;
    const float pc_irr  = r ? pc0 : pc1;

    const float dx = pr[0] - gx;
    const float dy = pr[1] - gy;
    const float dw = sqrtf(pr[2]) - sqrtf(gw);
    const float dh = sqrtf(pr[3]) - sqrtf(gh);
    const float coord = dx*dx + dy*dy + dw*dw + dh*dh;

    const float dr = pr[4] - max_iou;
    const float resp_l   = dr * dr;
    const float irresp_l = pc_irr * pc_irr;

    float cls = 0.0f;
    #pragma unroll
    for (int c = 10; c < 30; c++) {
        const float d = p[c] - g[c];
        cls = fmaf(d, d, cls);
    }

    return obj * (5.0f * coord + 2.0f * resp_l + irresp_l + cls)
         + 0.5f * no_obj_term;
}

__global__ __launch_bounds__(TPB)
void yolo_loss_bulk_pipe(const char* __restrict__ predb,
                         const char* __restrict__ gtb,
                         float* __restrict__ out,
                         int n_wtiles, int n_wpipes, float inv_batch)
{
    extern __shared__ char smem[];             // [4 warps][2 bufs][7680 B]
    __shared__ unsigned long long mbar_s[NWARPS_CTA * 2];

    const int tid  = threadIdx.x;
    const int lane = tid & 31;
    const int wid  = tid >> 5;
    char* wsm = smem + wid * WARP_SMEM_BYTES;

    // init per-warp mbarriers (one per buffer), arrive count = 1
    if (tid < NWARPS_CTA * 2) {
        unsigned mb = (unsigned)__cvta_generic_to_shared(&mbar_s[tid]);
        asm volatile("mbarrier.init.shared.b64 [%0], 1;" :: "r"(mb) : "memory");
    }
    __syncthreads();

    // ---- per-warp bulk stage: one 32-cell tile (pred+gt) into buffer `buf`
    // ONE UBLKCP per tensor instead of 240 LDGSTS -> removes the LSU floor.
    auto issue = [&](int tile, int buf) {
        if (lane == 0) {
            unsigned mb = (unsigned)__cvta_generic_to_shared(&mbar_s[wid * 2 + buf]);
            const char* psrc = predb + (long long)tile * WT_BYTES;
            const char* gsrc = gtb   + (long long)tile * WT_BYTES;
            unsigned dstp = (unsigned)__cvta_generic_to_shared(wsm + buf * STAGE_BYTES);
            unsigned dstg = dstp + WT_BYTES;
            asm volatile("mbarrier.arrive.expect_tx.shared::cta.b64 _, [%0], %1;"
                         :: "r"(mb), "r"((unsigned)STAGE_BYTES) : "memory");
            asm volatile(
                "cp.async.bulk.shared::cta.global.mbarrier::complete_tx::bytes "
                "[%0], [%1], %2, [%3];"
                :: "r"(dstp), "l"(psrc), "r"((unsigned)WT_BYTES), "r"(mb) : "memory");
            asm volatile(
                "cp.async.bulk.shared::cta.global.mbarrier::complete_tx::bytes "
                "[%0], [%1], %2, [%3];"
                :: "r"(dstg), "l"(gsrc), "r"((unsigned)WT_BYTES), "r"(mb) : "memory");
        }
    };

    auto wait_buf = [&](int buf, int phase) {
        unsigned mb = (unsigned)__cvta_generic_to_shared(&mbar_s[wid * 2 + buf]);
        unsigned done;
        asm volatile(
            "{\n\t.reg .pred p;\n\t"
            "mbarrier.try_wait.parity.acquire.cta.shared::cta.b64 p, [%1], %2;\n\t"
            "selp.b32 %0, 1, 0, p;\n\t}"
            : "=r"(done) : "r"(mb), "r"((unsigned)phase) : "memory");
        while (!done) {
            asm volatile(
                "{\n\t.reg .pred p;\n\t"
                "mbarrier.try_wait.parity.acquire.cta.shared::cta.b64 p, [%1], %2, 0x989680;\n\t"
                "selp.b32 %0, 1, 0, p;\n\t}"
                : "=r"(done) : "r"(mb), "r"((unsigned)phase) : "memory");
        }
    };

    float acc = 0.0f;
    const int gw = blockIdx.x * NWARPS_CTA + wid;   // global warp-pipeline id
    int t   = gw;
    int buf = 0;
    int ph0 = 0, ph1 = 0;                            // phase per buffer

    if (t < n_wtiles) issue(t, 0);

    while (t < n_wtiles) {
        const int tn = t + n_wpipes;
        if (tn < n_wtiles) issue(tn, buf ^ 1);

        const int ph = buf ? ph1 : ph0;
        wait_buf(buf, ph);                           // all lanes; acquire
        if (buf) ph1 ^= 1; else ph0 ^= 1;

        const float* base = reinterpret_cast<const float*>(wsm + buf * STAGE_BYTES);
        acc += cell_loss(base + lane * NCH,
                         base + (WT_BYTES / 4) + lane * NCH);

        __syncwarp();   // all lanes done reading buf before lane0 refills it
        buf ^= 1;
        t = tn;
    }

    // ---- per-warp then block reduction (deterministic) ----
    #pragma unroll
    for (int o = 16; o > 0; o >>= 1)
        acc += __shfl_down_sync(0xffffffffu, acc, o);

    __shared__ float s_warp[NWARPS_CTA];
    if (lane == 0) s_warp[wid] = acc;
    __syncthreads();

    __shared__ bool s_is_last;
    if (tid == 0) {
        g_partials[blockIdx.x] = s_warp[0] + s_warp[1] + s_warp[2] + s_warp[3];
        __threadfence();
        unsigned int done = atomicAdd(&g_count, 1u);
        s_is_last = (done == (unsigned int)(gridDim.x - 1));
    }
    __syncthreads();

    // ---- last block folds the partials (fixed order -> deterministic) ----
    if (s_is_last) {
        float v = 0.0f;
        for (int i = tid; i < (int)gridDim.x; i += TPB)
            v += g_partials[i];

        #pragma unroll
        for (int o = 16; o > 0; o >>= 1)
            v += __shfl_down_sync(0xffffffffu, v, o);

        if (lane == 0) s_warp[wid] = v;
        __syncthreads();
        if (tid == 0) {
            out[0] = (s_warp[0] + s_warp[1] + s_warp[2] + s_warp[3]) * inv_batch;
            g_count = 0;   // reset for next graph replay
        }
    }
}

extern "C" void kernel_launch(void* const* d_in, const int* in_sizes, int n_in,
                              void* d_out, int out_size)
{
    const char* predb = (const char*)d_in[0];
    const char* gtb   = (const char*)d_in[1];
    float* out = (float*)d_out;

    const int n_cells  = in_sizes[0] / NCH;       // 401408
    const int n_wtiles = n_cells / 32;            // 12544 (exact)
    const int n_wpipes = GRID_BLOCKS * NWARPS_CTA;// 1824
    const int batch    = n_cells / 49;            // 8192

    cudaFuncSetAttribute(yolo_loss_bulk_pipe,
                         cudaFuncAttributeMaxDynamicSharedMemorySize, SMEM_BYTES);

    yolo_loss_bulk_pipe<<<GRID_BLOCKS, TPB, SMEM_BYTES>>>(predb, gtb, out,
                                                          n_wtiles, n_wpipes,
                                                          1.0f / (float)batch);
}

// round 16
// speedup vs baseline: 1.1104x; 1.0216x over previous
#include <cuda_runtime.h>

// Fixed shapes: pred[8192,7,7,30], gt[8192,7,7,30]
// 401408 cells = 12544 warp-tiles of 32 cells
#define NCH        30
#define TPB        128
#define NWARPS_CTA 4
#define GRID_BLOCKS 456                       // 152 SMs * 3 CTAs -> one wave
#define WT_BYTES   3840                       // 32 cells * 30 ch * 4 B (per tensor)
#define STAGE_BYTES (2 * WT_BYTES)            // 7680 B (pred + gt)
#define WARP_SMEM_BYTES (2 * STAGE_BYTES)     // double buffer = 15360 B
#define SMEM_BYTES (NWARPS_CTA * WARP_SMEM_BYTES)   // 61440 B
#define MAX_PART   1024

__device__ float        g_partials[MAX_PART];
__device__ unsigned int g_count = 0;

__device__ __forceinline__ float cell_loss(const float* __restrict__ p,
                                           const float* __restrict__ g)
{
    const float gx = g[0], gy = g[1], gw = g[2], gh = g[3];
    const float obj   = (g[4] > 0.0f) ? 1.0f : 0.0f;
    const float noobj = 1.0f - obj;

    const float pc0 = p[4];
    const float pc1 = p[9];

    const float no_obj_term = noobj * (pc0 * pc0 + pc1 * pc1);

    const float ghw = 3.5f * gw, ghh = 3.5f * gh;
    const float gx1 = gx - ghw, gx2 = gx + ghw;
    const float gy1 = gy - ghh, gy2 = gy + ghh;
    const float a2  = 49.0f * gw * gh;

    float iou[2];
    #pragma unroll
    for (int b = 0; b < 2; b++) {
        const float cx = p[b*5+0], cy = p[b*5+1];
        const float w  = p[b*5+2], h  = p[b*5+3];
        const float hw = 3.5f * w, hh = 3.5f * h;
        const float iw = fmaxf(fminf(cx + hw, gx2) - fmaxf(cx - hw, gx1), 0.0f);
        const float ih = fmaxf(fminf(cy + hh, gy2) - fmaxf(cy - hh, gy1), 0.0f);
        const float inter = iw * ih;
        const float a1 = 49.0f * w * h;
        iou[b] = inter / (a1 + a2 - inter);
    }

    const int   r       = (iou[1] > iou[0]) ? 1 : 0;
    const float max_iou = fmaxf(iou[0], iou[1]);
    const float* pr     = p + r * 5;
    const float pc_irr  = r ? pc0 : pc1;

    const float dx = pr[0] - gx;
    const float dy = pr[1] - gy;
    const float dw = sqrtf(pr[2]) - sqrtf(gw);
    const float dh = sqrtf(pr[3]) - sqrtf(gh);
    const float coord = dx*dx + dy*dy + dw*dw + dh*dh;

    const float dr = pr[4] - max_iou;
    const float resp_l   = dr * dr;
    const float irresp_l = pc_irr * pc_irr;

    float cls = 0.0f;
    #pragma unroll
    for (int c = 10; c < 30; c++) {
        const float d = p[c] - g[c];
        cls = fmaf(d, d, cls);
    }

    return obj * (5.0f * coord + 2.0f * resp_l + irresp_l + cls)
         + 0.5f * no_obj_term;
}

__global__ __launch_bounds__(TPB)
void yolo_loss_bulk_pipe(const char* __restrict__ predb,
                         const char* __restrict__ gtb,
                         float* __restrict__ out,
                         int n_wtiles, int n_wpipes, float inv_batch)
{
    extern __shared__ char smem[];             // [4 warps][2 bufs][7680 B]
    __shared__ unsigned long long mbar_s[NWARPS_CTA * 2];

    const int tid  = threadIdx.x;
    const int lane = tid & 31;
    const int wid  = tid >> 5;
    char* wsm = smem + wid * WARP_SMEM_BYTES;

    // init per-warp mbarriers (one per buffer), arrive count = 1
    if (tid < NWARPS_CTA * 2) {
        unsigned mb = (unsigned)__cvta_generic_to_shared(&mbar_s[tid]);
        asm volatile("mbarrier.init.shared.b64 [%0], 1;" :: "r"(mb) : "memory");
    }
    __syncthreads();

    // ---- per-warp bulk stage: one 32-cell tile (pred+gt) into buffer `buf`
    // ONE bulk copy per tensor instead of 240 LDGSTS.
    auto issue = [&](int tile, int buf) {
        if (lane == 0) {
            unsigned mb = (unsigned)__cvta_generic_to_shared(&mbar_s[wid * 2 + buf]);
            const char* psrc = predb + (long long)tile * WT_BYTES;
            const char* gsrc = gtb   + (long long)tile * WT_BYTES;
            unsigned dstp = (unsigned)__cvta_generic_to_shared(wsm + buf * STAGE_BYTES);
            unsigned dstg = dstp + WT_BYTES;
            asm volatile("mbarrier.arrive.expect_tx.shared::cta.b64 _, [%0], %1;"
                         :: "r"(mb), "r"((unsigned)STAGE_BYTES) : "memory");
            asm volatile(
                "cp.async.bulk.shared::cta.global.mbarrier::complete_tx::bytes "
                "[%0], [%1], %2, [%3];"
                :: "r"(dstp), "l"(psrc), "r"((unsigned)WT_BYTES), "r"(mb) : "memory");
            asm volatile(
                "cp.async.bulk.shared::cta.global.mbarrier::complete_tx::bytes "
                "[%0], [%1], %2, [%3];"
                :: "r"(dstg), "l"(gsrc), "r"((unsigned)WT_BYTES), "r"(mb) : "memory");
        }
    };

    auto wait_buf = [&](int buf, int phase) {
        unsigned mb = (unsigned)__cvta_generic_to_shared(&mbar_s[wid * 2 + buf]);
        unsigned done;
        asm volatile(
            "{\n\t.reg .pred p;\n\t"
            "mbarrier.try_wait.parity.acquire.cta.shared::cta.b64 p, [%1], %2;\n\t"
            "selp.b32 %0, 1, 0, p;\n\t}"
            : "=r"(done) : "r"(mb), "r"((unsigned)phase) : "memory");
        while (!done) {
            asm volatile(
                "{\n\t.reg .pred p;\n\t"
                "mbarrier.try_wait.parity.acquire.cta.shared::cta.b64 p, [%1], %2, 0x989680;\n\t"
                "selp.b32 %0, 1, 0, p;\n\t}"
                : "=r"(done) : "r"(mb), "r"((unsigned)phase) : "memory");
        }
    };

    float acc = 0.0f;
    const int gw = blockIdx.x * NWARPS_CTA + wid;   // global warp-pipeline id
    int t   = gw;
    int buf = 0;
    int ph0 = 0, ph1 = 0;                            // phase per buffer

    if (t < n_wtiles) issue(t, 0);

    while (t < n_wtiles) {
        const int tn = t + n_wpipes;
        if (tn < n_wtiles) issue(tn, buf ^ 1);

        const int ph = buf ? ph1 : ph0;
        wait_buf(buf, ph);                           // all lanes; acquire
        if (buf) ph1 ^= 1; else ph0 ^= 1;

        const float* base = reinterpret_cast<const float*>(wsm + buf * STAGE_BYTES);
        acc += cell_loss(base + lane * NCH,
                         base + (WT_BYTES / 4) + lane * NCH);

        __syncwarp();   // all lanes done reading buf before lane0 refills it
        buf ^= 1;
        t = tn;
    }

    // ---- per-warp then block reduction (deterministic) ----
    #pragma unroll
    for (int o = 16; o > 0; o >>= 1)
        acc += __shfl_down_sync(0xffffffffu, acc, o);

    __shared__ float s_warp[NWARPS_CTA];
    if (lane == 0) s_warp[wid] = acc;
    __syncthreads();

    __shared__ bool s_is_last;
    if (tid == 0) {
        g_partials[blockIdx.x] = s_warp[0] + s_warp[1] + s_warp[2] + s_warp[3];
        __threadfence();
        unsigned int done = atomicAdd(&g_count, 1u);
        s_is_last = (done == (unsigned int)(gridDim.x - 1));
    }
    __syncthreads();

    // ---- last block folds the partials (fixed order -> deterministic) ----
    if (s_is_last) {
        float v = 0.0f;
        for (int i = tid; i < (int)gridDim.x; i += TPB)
            v += g_partials[i];

        #pragma unroll
        for (int o = 16; o > 0; o >>= 1)
            v += __shfl_down_sync(0xffffffffu, v, o);

        if (lane == 0) s_warp[wid] = v;
        __syncthreads();
        if (tid == 0) {
            out[0] = (s_warp[0] + s_warp[1] + s_warp[2] + s_warp[3]) * inv_batch;
            g_count = 0;   // reset for next graph replay
        }
    }
}

extern "C" void kernel_launch(void* const* d_in, const int* in_sizes, int n_in,
                              void* d_out, int out_size)
{
    const char* predb = (const char*)d_in[0];
    const char* gtb   = (const char*)d_in[1];
    float* out = (float*)d_out;

    const int n_cells  = in_sizes[0] / NCH;       // 401408
    const int n_wtiles = n_cells / 32;            // 12544 (exact)
    const int n_wpipes = GRID_BLOCKS * NWARPS_CTA;// 1824
    const int batch    = n_cells / 49;            // 8192

    cudaFuncSetAttribute(yolo_loss_bulk_pipe,
                         cudaFuncAttributeMaxDynamicSharedMemorySize, SMEM_BYTES);

    yolo_loss_bulk_pipe<<<GRID_BLOCKS, TPB, SMEM_BYTES>>>(predb, gtb, out,
                                                          n_wtiles, n_wpipes,
                                                          1.0f / (float)batch);
}